// round 1
// baseline (speedup 1.0000x reference)
#include <cuda_runtime.h>

// Problem constants (fixed by the reference)
#define N_LAYERS 12
#define D_SAE    16384
#define D_MODEL  768
#define NNZ      131072

#define VEC      (D_MODEL / 4)   // 192 float4 per row
#define WARPS_PER_BLOCK 8
#define THREADS (WARPS_PER_BLOCK * 32)

__global__ __launch_bounds__(THREADS)
void gather_scale_kernel(const float4* __restrict__ W,      // [N_LAYERS*D_SAE, 192]
                         const float*  __restrict__ vals,   // [NNZ]
                         const int*    __restrict__ lidx,   // [NNZ]
                         const int*    __restrict__ fidx,   // [NNZ]
                         float4*       __restrict__ out)    // [NNZ, 192]
{
    const int warp_in_blk = threadIdx.x >> 5;
    const int lane        = threadIdx.x & 31;
    const int nz          = blockIdx.x * WARPS_PER_BLOCK + warp_in_blk;
    if (nz >= NNZ) return;

    const float v = __ldg(&vals[nz]);
    const long  row = (long)__ldg(&lidx[nz]) * D_SAE + (long)__ldg(&fidx[nz]);

    const float4* __restrict__ src = W   + row * (long)VEC;
    float4*       __restrict__ dst = out + (long)nz * (long)VEC;

    // 192 float4 per row, 32 lanes -> 6 per lane, fully unrolled for MLP
    #pragma unroll
    for (int i = 0; i < VEC / 32; ++i) {
        const int idx = lane + i * 32;
        float4 a = __ldg(&src[idx]);
        a.x *= v; a.y *= v; a.z *= v; a.w *= v;
        dst[idx] = a;
    }
}

extern "C" void kernel_launch(void* const* d_in, const int* in_sizes, int n_in,
                              void* d_out, int out_size)
{
    // metadata order: W_D (f32), values (f32), layer_idx (i32), pos_idx (i32), feat_idx (i32)
    const float4* W    = (const float4*)d_in[0];
    const float*  vals = (const float*)d_in[1];
    const int*    lidx = (const int*)d_in[2];
    // pos_idx (d_in[3]) is unused by the reference computation
    const int*    fidx = (const int*)d_in[4];
    float4*       out  = (float4*)d_out;

    const int grid = NNZ / WARPS_PER_BLOCK;   // 16384 blocks
    gather_scale_kernel<<<grid, THREADS>>>(W, vals, lidx, fidx, out);
}

// round 3
// speedup vs baseline: 1.0089x; 1.0089x over previous
#include <cuda_runtime.h>

// Problem constants (fixed by the reference)
#define N_LAYERS 12
#define D_SAE    16384
#define D_MODEL  768
#define NNZ      131072

#define VEC      (D_MODEL / 4)   // 192 float4 per row
#define WARPS_PER_BLOCK 8
#define THREADS (WARPS_PER_BLOCK * 32)

__global__ __launch_bounds__(THREADS)
void gather_scale_kernel(const float4* __restrict__ W,      // [N_LAYERS*D_SAE, 192]
                         const float*  __restrict__ vals,   // [NNZ]
                         const int*    __restrict__ lidx,   // [NNZ]
                         const int*    __restrict__ fidx,   // [NNZ]
                         float4*       __restrict__ out)    // [NNZ, 192]
{
    const int warp_in_blk = threadIdx.x >> 5;
    const int lane        = threadIdx.x & 31;
    const int nz          = blockIdx.x * WARPS_PER_BLOCK + warp_in_blk;
    if (nz >= NNZ) return;

    const float v = __ldg(&vals[nz]);
    const long  row = (long)__ldg(&lidx[nz]) * D_SAE + (long)__ldg(&fidx[nz]);

    const float4* __restrict__ src = W   + row * (long)VEC;
    float4*       __restrict__ dst = out + (long)nz * (long)VEC;

    // 192 float4 per row, 32 lanes -> 6 per lane, fully unrolled for MLP.
    // Loads: default L2-cached (duplicate rows reuse from L2).
    // Stores: evict-first (__stcs) so the 403MB output stream doesn't thrash
    //         the resident decoder slab in L2.
    #pragma unroll
    for (int i = 0; i < VEC / 32; ++i) {
        const int idx = lane + i * 32;
        float4 a = __ldg(&src[idx]);
        a.x *= v; a.y *= v; a.z *= v; a.w *= v;
        __stcs(&dst[idx], a);
    }
}

extern "C" void kernel_launch(void* const* d_in, const int* in_sizes, int n_in,
                              void* d_out, int out_size)
{
    // metadata order: W_D (f32), values (f32), layer_idx (i32), pos_idx (i32), feat_idx (i32)
    const float4* W    = (const float4*)d_in[0];
    const float*  vals = (const float*)d_in[1];
    const int*    lidx = (const int*)d_in[2];
    // pos_idx (d_in[3]) is unused by the reference computation
    const int*    fidx = (const int*)d_in[4];
    float4*       out  = (float4*)d_out;

    const int grid = NNZ / WARPS_PER_BLOCK;   // 16384 blocks
    gather_scale_kernel<<<grid, THREADS>>>(W, vals, lidx, fidx, out);
}